// round 16
// baseline (speedup 1.0000x reference)
#include <cuda_runtime.h>
#include <cuda_fp16.h>
#include <cstdint>

// NT-Xent loss, single fused kernel. Phase 1: each CTA normalizes its 64 rows
// (fp32 -> fp16, A copy pre-scaled by log2(e)/T), grid-wide spin barrier
// (128 CTAs, all resident). Phase 2: tcgen05 SS MMA (fp32 D), N=256
// super-tiles, LDTM halves pipelined (r1 issued before r0 consumed),
// B-copy in epilogue shadow, fused pos capture + finalize.

#define NTOT 8192
#define HALF_N 4096
#define DDIM 128
#define SCALE_EX2 20.6099291555566218f   // log2(e)/0.07
#define LN2F 0.6931471805599453f
#define NSUP 16
#define NTHR 512
#define NCTA 128

#if defined(__CUDA_ARCH__) && (defined(__CUDA_ARCH_FEAT_SM103_ALL) || defined(__CUDA_ARCH_SPECIFIC__))
#define HAS_TCGEN05 1
#else
#define HAS_TCGEN05 0
#endif

__device__ __half g_ZA[NTOT * DDIM];   // unit rows * SCALE_EX2 (A operand)
__device__ __half g_ZB[NTOT * DDIM];   // unit rows (B operand)
__device__ float g_rowsum[NTOT];
__device__ float g_posv[NTOT];
__device__ float g_accum;
__device__ int   g_outcnt;
__device__ int   g_sync;
__device__ int   g_blkdone[64];

// ---------------------------------------------------------------- common utils
__device__ __forceinline__ float fexp2(float x) {
    float y;
    asm("ex2.approx.f32 %0, %1;" : "=f"(y) : "f"(x));
    return y;
}
__device__ __forceinline__ void cp_async16(uint32_t dst, const void* src) {
    asm volatile("cp.async.cg.shared.global [%0], [%1], 16;"
                 :: "r"(dst), "l"(src) : "memory");
}
__device__ __forceinline__ void cp_commit() {
    asm volatile("cp.async.commit_group;" ::: "memory");
}
template <int N>
__device__ __forceinline__ void cp_wait() {
    asm volatile("cp.async.wait_group %0;" :: "n"(N) : "memory");
}

// ---------------------------------------------------------------- kernel 2
#define SM_A    0
#define SM_B0   32768
#define SM_B1   98304
#define SM_CTRL 163840
#define SMEM_REQ (163904 + 1024)

#if HAS_TCGEN05
// ---------------- tcgen05 helpers (sm_103a pass only) ----------------
__device__ __forceinline__ uint32_t elect_one() {
    uint32_t p;
    asm volatile("{\n\t.reg .pred p;\n\telect.sync _|p, 0xFFFFFFFF;\n\t"
                 "selp.b32 %0, 1, 0, p;\n\t}" : "=r"(p));
    return p;
}
__device__ __forceinline__ void mbar_init(uint32_t a, uint32_t cnt) {
    asm volatile("mbarrier.init.shared.b64 [%0], %1;" :: "r"(a), "r"(cnt) : "memory");
}
__device__ __forceinline__ void mbar_inval(uint32_t a) {
    asm volatile("mbarrier.inval.shared.b64 [%0];" :: "r"(a) : "memory");
}
__device__ __forceinline__ void mbar_wait(uint32_t a, uint32_t phase) {
    asm volatile(
        "{\n\t.reg .pred P;\n\t"
        "W%=:\n\t"
        "mbarrier.try_wait.parity.acquire.cta.shared::cta.b64 P, [%0], %1, 0x989680;\n\t"
        "@P bra D%=;\n\t"
        "bra W%=;\n\t"
        "D%=:\n\t}"
        :: "r"(a), "r"(phase) : "memory");
}
__device__ __forceinline__ void tc_alloc(uint32_t smem_res, uint32_t ncols) {
    asm volatile("tcgen05.alloc.cta_group::1.sync.aligned.shared::cta.b32 [%0], %1;"
                 :: "r"(smem_res), "r"(ncols) : "memory");
}
__device__ __forceinline__ void tc_dealloc(uint32_t tmem, uint32_t ncols) {
    asm volatile("tcgen05.dealloc.cta_group::1.sync.aligned.b32 %0, %1;"
                 :: "r"(tmem), "r"(ncols));
}
__device__ __forceinline__ void tc_commit(uint32_t mbar) {
    asm volatile("tcgen05.commit.cta_group::1.mbarrier::arrive::one.shared::cluster.b64 [%0];"
                 :: "r"(mbar) : "memory");
}
__device__ __forceinline__ void tc_fence_before() {
    asm volatile("tcgen05.fence::before_thread_sync;" ::: "memory");
}
__device__ __forceinline__ void tc_fence_after() {
    asm volatile("tcgen05.fence::after_thread_sync;" ::: "memory");
}
__device__ __forceinline__ void tc_wait_ld() {
    asm volatile("tcgen05.wait::ld.sync.aligned;" ::: "memory");
}
__device__ __forceinline__ void fence_proxy_async_cta() {
    asm volatile("fence.proxy.async.shared::cta;" ::: "memory");
}
__device__ __forceinline__ void tc_mma_f16_ss(uint32_t d, uint64_t ad, uint64_t bd,
                                              uint32_t idesc, uint32_t en) {
    asm volatile(
        "{\n\t.reg .pred p;\n\tsetp.ne.u32 p, %4, 0;\n\t"
        "tcgen05.mma.cta_group::1.kind::f16 [%0], %1, %2, %3, {%5, %5, %5, %5}, p;\n\t}"
        :: "r"(d), "l"(ad), "l"(bd), "r"(idesc), "r"(en), "r"(0u) : "memory");
}
__device__ __forceinline__ void tc_ld_x32(uint32_t* r, uint32_t a) {
    asm volatile(
        "tcgen05.ld.sync.aligned.32x32b.x32.b32 "
        "{%0,%1,%2,%3,%4,%5,%6,%7,%8,%9,%10,%11,%12,%13,%14,%15,"
        "%16,%17,%18,%19,%20,%21,%22,%23,%24,%25,%26,%27,%28,%29,%30,%31}, [%32];"
        : "=r"(r[0]), "=r"(r[1]), "=r"(r[2]), "=r"(r[3]), "=r"(r[4]), "=r"(r[5]),
          "=r"(r[6]), "=r"(r[7]), "=r"(r[8]), "=r"(r[9]), "=r"(r[10]), "=r"(r[11]),
          "=r"(r[12]), "=r"(r[13]), "=r"(r[14]), "=r"(r[15]), "=r"(r[16]), "=r"(r[17]),
          "=r"(r[18]), "=r"(r[19]), "=r"(r[20]), "=r"(r[21]), "=r"(r[22]), "=r"(r[23]),
          "=r"(r[24]), "=r"(r[25]), "=r"(r[26]), "=r"(r[27]), "=r"(r[28]), "=r"(r[29]),
          "=r"(r[30]), "=r"(r[31])
        : "r"(a));
}
// SMEM desc: SW128, version 1 (Blackwell), SBO=64, LBO=1 (K-major)
static __device__ __forceinline__ uint64_t mk_desc(uint32_t addr) {
    return (2ull << 61) | (1ull << 46) | (64ull << 32) | (1ull << 16) |
           ((uint64_t)(addr >> 4) & 0x3FFF);
}
// idesc: dtype F32 (bit4), atype/btype F16(=0), N=256, M=128
#define IDESC ((1u << 4) | (32u << 17) | (8u << 24))

// A tile: 128 rows, atom-col stride 16KB (from g_ZA, pre-scaled)
__device__ __forceinline__ void copy_tileA(uint32_t sm_dst, int gRow0, int tid) {
    const char* gbase = (const char*)g_ZA + (size_t)gRow0 * DDIM * 2;
#pragma unroll
    for (int i = 0; i < 2048 / NTHR; i++) {
        int idx = i * NTHR + tid;
        int r = idx >> 4, c = idx & 15;
        uint32_t off = (uint32_t)(r * 128 + (c & 7) * 16);
        uint32_t dst = sm_dst + (uint32_t)((c >> 3) * 16384) +
                       (off ^ ((off >> 3) & 0x70));
        cp_async16(dst, gbase + r * 256 + c * 16);
    }
}
// B super-tile: 256 rows, atom-col stride 32KB (from g_ZB, unit)
__device__ __forceinline__ void copy_tileB(uint32_t sm_dst, int gRow0, int tid) {
    const char* gbase = (const char*)g_ZB + (size_t)gRow0 * DDIM * 2;
#pragma unroll
    for (int i = 0; i < 4096 / NTHR; i++) {
        int idx = i * NTHR + tid;
        int r = idx >> 4, c = idx & 15;
        uint32_t off = (uint32_t)(r * 128 + (c & 7) * 16);
        uint32_t dst = sm_dst + (uint32_t)((c >> 3) * 32768) +
                       (off ^ ((off >> 3) & 0x70));
        cp_async16(dst, gbase + r * 256 + c * 16);
    }
}

// FAST: 32 PRE-SCALED fp32 logits -> sum of exp2 (no FMUL, no compares).
__device__ __forceinline__ float expfast32(const uint32_t* r) {
    __half2 s0 = __float2half2_rn(0.0f), s1 = s0;
#pragma unroll
    for (int w = 0; w < 32; w += 4) {
        uint32_t p0, p1, e0, e1;
        asm("cvt.rn.f16x2.f32 %0, %1, %2;" : "=r"(p0)
            : "f"(__uint_as_float(r[w + 1])), "f"(__uint_as_float(r[w])));
        asm("cvt.rn.f16x2.f32 %0, %1, %2;" : "=r"(p1)
            : "f"(__uint_as_float(r[w + 3])), "f"(__uint_as_float(r[w + 2])));
        asm("ex2.approx.f16x2 %0, %1;" : "=r"(e0) : "r"(p0));
        asm("ex2.approx.f16x2 %0, %1;" : "=r"(e1) : "r"(p1));
        s0 = __hadd2(s0, *(__half2*)&e0);
        s1 = __hadd2(s1, *(__half2*)&e1);
    }
    float2 f = __half22float2(__hadd2(s0, s1));
    return f.x + f.y;
}

// SLOW (diag/pos tiles): pos capture (scaled) + positional diag mask.
__device__ __forceinline__ float expslow32(const uint32_t* r, int pm, int dm,
                                           float* posDot) {
    __half2 s0 = __float2half2_rn(0.0f), s1 = s0;
#pragma unroll
    for (int w = 0; w < 32; w += 2) {
        float v0 = __uint_as_float(r[w]);
        float v1 = __uint_as_float(r[w + 1]);
        if (w == pm)     *posDot = v0;
        if (w + 1 == pm) *posDot = v1;
        float x0 = (w == dm)     ? -1e4f : v0;
        float x1 = (w + 1 == dm) ? -1e4f : v1;
        uint32_t p, e;
        asm("cvt.rn.f16x2.f32 %0, %1, %2;" : "=r"(p) : "f"(x1), "f"(x0));
        asm("ex2.approx.f16x2 %0, %1;" : "=r"(e) : "r"(p));
        if (w & 2) s1 = __hadd2(s1, *(__half2*)&e);
        else       s0 = __hadd2(s0, *(__half2*)&e);
    }
    float2 f = __half22float2(__hadd2(s0, s1));
    return f.x + f.y;
}
#endif  // HAS_TCGEN05

#if !HAS_TCGEN05
#define PAD 136
__device__ __forceinline__ void ldmatrix_x4(uint32_t* r, const void* p) {
    uint32_t sa = (uint32_t)__cvta_generic_to_shared(p);
    asm volatile("ldmatrix.sync.aligned.m8n8.x4.shared.b16 {%0,%1,%2,%3}, [%4];"
                 : "=r"(r[0]), "=r"(r[1]), "=r"(r[2]), "=r"(r[3]) : "r"(sa));
}
__device__ __forceinline__ void mma16816(float* d, const uint32_t* a,
                                          uint32_t b0, uint32_t b1) {
    asm volatile(
        "mma.sync.aligned.m16n8k16.row.col.f32.f16.f16.f32 "
        "{%0,%1,%2,%3}, {%4,%5,%6,%7}, {%8,%9}, {%0,%1,%2,%3};"
        : "+f"(d[0]), "+f"(d[1]), "+f"(d[2]), "+f"(d[3])
        : "r"(a[0]), "r"(a[1]), "r"(a[2]), "r"(a[3]), "r"(b0), "r"(b1));
}
#endif

__global__ void __launch_bounds__(NTHR, 1) simlse_tc(const float* __restrict__ zi,
                                                     const float* __restrict__ zj,
                                                     float* __restrict__ out) {
    extern __shared__ char dsm[];
    int tid = threadIdx.x;
    int lane = tid & 31;
    int wid = tid >> 5;
    int rowBase = blockIdx.x * 128;

    // ================= Phase 1: fused normalization + grid barrier ==========
    {
        int cta = blockIdx.x * 2 + blockIdx.y;       // 0..127
        // 16 warps x 4 rows = 64 rows per CTA
#pragma unroll
        for (int i = 0; i < 64 / (NTHR / 32); i++) {
            int row = cta * 64 + i * (NTHR / 32) + wid;
            const float* src = (row < HALF_N) ? (zi + (size_t)row * DDIM)
                                              : (zj + (size_t)(row - HALF_N) * DDIM);
            float4 v = ((const float4*)src)[lane];
            float ss = v.x * v.x + v.y * v.y + v.z * v.z + v.w * v.w;
#pragma unroll
            for (int off = 16; off > 0; off >>= 1)
                ss += __shfl_xor_sync(0xffffffffu, ss, off);
            float s = rsqrtf(fmaxf(ss, 1e-24f));
            float sA = s * SCALE_EX2;
            __half2* dstB = (__half2*)(g_ZB + (size_t)row * DDIM);
            dstB[lane * 2 + 0] = __floats2half2_rn(v.x * s, v.y * s);
            dstB[lane * 2 + 1] = __floats2half2_rn(v.z * s, v.w * s);
            __half2* dstA = (__half2*)(g_ZA + (size_t)row * DDIM);
            dstA[lane * 2 + 0] = __floats2half2_rn(v.x * sA, v.y * sA);
            dstA[lane * 2 + 1] = __floats2half2_rn(v.z * sA, v.w * sA);
            if (lane == 0) g_rowsum[row] = 0.0f;
        }
        __threadfence();
        __syncthreads();
        if (tid == 0) {
            atomicAdd(&g_sync, 1);
            while (atomicAdd(&g_sync, 0) < NCTA) { }
        }
        __syncthreads();
        __threadfence();
    }

#if HAS_TCGEN05
    // ================= Phase 2: tcgen05 body =================
    uint32_t raw = (uint32_t)__cvta_generic_to_shared(dsm);
    uint32_t base = (raw + 1023u) & ~1023u;
    int sup0 = blockIdx.y * NSUP;

    if (wid == 0) tc_alloc(base + SM_CTRL, 512);
    if (tid == 0) { mbar_init(base + SM_CTRL + 8, 1); mbar_init(base + SM_CTRL + 16, 1); }
    __syncthreads();
    uint32_t tmem;
    asm volatile("ld.shared.b32 %0, [%1];" : "=r"(tmem) : "r"(base + SM_CTRL));

    copy_tileA(base + SM_A, rowBase, tid);
    copy_tileB(base + SM_B0, sup0 * 256, tid);
    cp_commit();

    uint64_t descA = mk_desc(base + SM_A);
    const uint32_t kOffA[8] = {0, 2, 4, 6, 1024, 1026, 1028, 1030};
    const uint32_t kOffB[8] = {0, 2, 4, 6, 2048, 2050, 2052, 2054};

    uint32_t phase0 = 0, phase1 = 0;
    float rowAcc = 0.0f, posDot = 0.0f;
    bool havePos = false;
    int myRow = rowBase + (wid & 3) * 32 + lane;
    int partner = myRow ^ 4096;
    int partnerBase = rowBase ^ 4096;
    uint32_t tsub = ((uint32_t)(wid & 3)) << 21;
    uint32_t wordOff = (uint32_t)((wid >> 2) * 64);
    int colOff = (wid >> 2) * 64;

    for (int t = 0; t < NSUP; t++) {
        int buf = t & 1;
        cp_wait<0>();
        fence_proxy_async_cta();
        __syncthreads();
        if (wid == 0 && elect_one()) {
            uint64_t descB = mk_desc(base + (buf ? SM_B1 : SM_B0));
            uint32_t dAddr = tmem + buf * 256;
#pragma unroll
            for (int ks = 0; ks < 8; ks++)
                tc_mma_f16_ss(dAddr, descA + kOffA[ks], descB + kOffB[ks], IDESC, ks > 0);
            tc_commit(base + SM_CTRL + 8 + 8 * buf);
        }
        if (t > 0) {
            int pb = (t - 1) & 1;
            mbar_wait(base + SM_CTRL + 8 + 8 * pb, pb ? phase1 : phase0);
            if (pb) phase1 ^= 1; else phase0 ^= 1;
            tc_fence_after();
            uint32_t dPrev = tmem + (uint32_t)pb * 256 + tsub + wordOff;
            uint32_t r0[32];
            tc_ld_x32(r0, dPrev);
            if (t < NSUP - 1) {
                copy_tileB(base + (((t + 1) & 1) ? SM_B1 : SM_B0),
                           (sup0 + t + 1) * 256, tid);
                cp_commit();
            }
            int colBase = (sup0 + t - 1) * 256;
            bool special = ((unsigned)(rowBase - colBase) < 256u) ||
                           ((unsigned)(partnerBase - colBase) < 256u);
            int gc0 = colBase + colOff;
            int pm = partner - gc0;
            int dm = ((unsigned)(rowBase - colBase) < 256u) ? (myRow - gc0) : -100;
            tc_wait_ld();           // r0 ready
            uint32_t r1[32];
            tc_ld_x32(r1, dPrev + 32);   // r1 drains while r0 is consumed
            if (special) {
                rowAcc += expslow32(r0, pm, dm, &posDot);
                if ((unsigned)pm < 64u) havePos = true;
            } else {
                rowAcc += expfast32(r0);
            }
            tc_wait_ld();           // r1 ready
            if (special) {
                rowAcc += expslow32(r1, pm - 32, dm - 32, &posDot);
            } else {
                rowAcc += expfast32(r1);
            }
            tc_fence_before();
        } else {
            copy_tileB(base + SM_B1, (sup0 + 1) * 256, tid);
            cp_commit();
        }
    }
    // final epilogue (t = NSUP-1)
    {
        int pt = NSUP - 1;
        int pb = pt & 1;
        mbar_wait(base + SM_CTRL + 8 + 8 * pb, pb ? phase1 : phase0);
        tc_fence_after();
        int colBase = (sup0 + pt) * 256;
        uint32_t dPrev = tmem + (uint32_t)pb * 256 + tsub + wordOff;
        bool special = ((unsigned)(rowBase - colBase) < 256u) ||
                       ((unsigned)(partnerBase - colBase) < 256u);
        int gc0 = colBase + colOff;
        int pm = partner - gc0;
        int dm = ((unsigned)(rowBase - colBase) < 256u) ? (myRow - gc0) : -100;
        uint32_t r0[32];
        tc_ld_x32(r0, dPrev);
        tc_wait_ld();
        uint32_t r1[32];
        tc_ld_x32(r1, dPrev + 32);
        if (special) {
            rowAcc += expslow32(r0, pm, dm, &posDot);
            if ((unsigned)pm < 64u) havePos = true;
        } else {
            rowAcc += expfast32(r0);
        }
        tc_wait_ld();
        if (special) {
            rowAcc += expslow32(r1, pm - 32, dm - 32, &posDot);
        } else {
            rowAcc += expfast32(r1);
        }
        tc_fence_before();
    }

    atomicAdd(&g_rowsum[myRow], rowAcc);
    if (havePos) g_posv[myRow] = posDot;

    __syncthreads();
    if (tid == 0) { mbar_inval(base + SM_CTRL + 8); mbar_inval(base + SM_CTRL + 16); }
    __syncthreads();
    if (wid == 0) tc_dealloc(tmem, 512);

#else
    // ================= mma.sync fallback body (warps 8-15 mostly idle) =======
#define NCOLT_FB 32
    __half* sT = (__half*)dsm;
    int warpM = wid & 3;
    int warpN = wid >> 2;
    int mBase = warpM * 32;
    int nBase = warpN * 64;

    for (int idx = tid; idx < 2048; idx += NTHR) {
        int r = idx >> 4, c = idx & 15;
        *(int4*)(&sT[r * PAD + c * 8]) =
            ((const int4*)(g_ZB + (size_t)rowBase * DDIM))[r * 16 + c];
    }
    __syncthreads();

    uint32_t aF[8][2][4];
    if (wid < 8) {
#pragma unroll
        for (int ks = 0; ks < 8; ks++)
#pragma unroll
            for (int am = 0; am < 2; am++) {
                const __half* p =
                    &sT[(mBase + am * 16 + (lane & 15)) * PAD + ks * 16 + (lane >> 4) * 8];
                ldmatrix_x4(aF[ks][am], p);
            }
    }
    __syncthreads();

    float rowAcc[2][2] = {{0.f, 0.f}, {0.f, 0.f}};

    for (int ct = 0; ct < NCOLT_FB; ct++) {
        int colBase = blockIdx.y * (NCOLT_FB * 128) + ct * 128;
        for (int idx = tid; idx < 2048; idx += NTHR) {
            int r = idx >> 4, c = idx & 15;
            *(int4*)(&sT[r * PAD + c * 8]) =
                ((const int4*)(g_ZB + (size_t)colBase * DDIM))[r * 16 + c];
        }
        __syncthreads();

        if (wid < 8) {
            float acc[2][8][4];
#pragma unroll
            for (int am = 0; am < 2; am++)
#pragma unroll
                for (int an = 0; an < 8; an++)
#pragma unroll
                    for (int v = 0; v < 4; v++) acc[am][an][v] = 0.0f;

#pragma unroll
            for (int ks = 0; ks < 8; ks++) {
                uint32_t bF[4][4];
#pragma unroll
                for (int bn = 0; bn < 4; bn++) {
                    const __half* p =
                        &sT[(nBase + bn * 16 + (lane & 15)) * PAD + ks * 16 + (lane >> 4) * 8];
                    ldmatrix_x4(bF[bn], p);
                }
#pragma unroll
                for (int am = 0; am < 2; am++)
#pragma unroll
                    for (int an = 0; an < 8; an++) {
                        uint32_t b0 = bF[an >> 1][(an & 1)];
                        uint32_t b1 = bF[an >> 1][2 + (an & 1)];
                        mma16816(acc[am][an], aF[ks][am], b0, b1);
                    }
            }

            bool diag = (rowBase == colBase);
#pragma unroll
            for (int am = 0; am < 2; am++)
#pragma unroll
                for (int an = 0; an < 8; an++)
#pragma unroll
                    for (int v = 0; v < 4; v++) {
                        float a = acc[am][an][v];
                        int rl = mBase + am * 16 + (lane >> 2) + ((v >> 1) << 3);
                        int cl = nBase + an * 8 + ((lane & 3) << 1) + (v & 1);
                        int grow = rowBase + rl;
                        int gcol = colBase + cl;
                        if (gcol == (grow ^ 4096)) g_posv[grow] = a * SCALE_EX2;
                        float e = fexp2(a * SCALE_EX2);
                        if (diag && rl == cl) e = 0.0f;
                        rowAcc[am][v >> 1] += e;
                    }
        }
        __syncthreads();
    }

    if (wid < 8) {
#pragma unroll
        for (int am = 0; am < 2; am++)
#pragma unroll
            for (int h = 0; h < 2; h++) {
                float r = rowAcc[am][h];
                r += __shfl_xor_sync(0xffffffffu, r, 1);
                r += __shfl_xor_sync(0xffffffffu, r, 2);
                if ((lane & 3) == 0) {
                    int gr = rowBase + mBase + am * 16 + (lane >> 2) + h * 8;
                    atomicAdd(&g_rowsum[gr], r);
                }
            }
    }
#endif

    // ============== shared tail: last CTA of row-block reduces ==============
    __shared__ int lastFlag;
    __shared__ float red[16];
    __threadfence();
    __syncthreads();
    if (tid == 0) {
        int old = atomicAdd(&g_blkdone[blockIdx.x], 1);
        lastFlag = (old == (int)gridDim.y - 1) ? 1 : 0;
    }
    __syncthreads();
    if (lastFlag) {
        __threadfence();
        float v = 0.0f;
        if (tid < 128) {
            int row = rowBase + tid;
            float rs = *(volatile float*)&g_rowsum[row];
            float pd = *(volatile float*)&g_posv[row];   // pre-scaled by SCALE_EX2
            v = __logf(rs) - pd * LN2F;
        }
#pragma unroll
        for (int off = 16; off > 0; off >>= 1)
            v += __shfl_xor_sync(0xffffffffu, v, off);
        if (lane == 0 && wid < 16) red[wid] = v;
        __syncthreads();
        if (tid == 0) {
            g_blkdone[blockIdx.x] = 0;   // reset for next graph replay
            float b = 0.0f;
#pragma unroll
            for (int w = 0; w < NTHR / 32; w++) b += red[w];
            atomicAdd(&g_accum, b);
            __threadfence();
            int old2 = atomicAdd(&g_outcnt, 1);
            if (old2 == 63) {
                out[0] = atomicAdd(&g_accum, 0.0f) * (1.0f / (float)NTOT);
                __threadfence();
                g_accum = 0.0f;          // reset globals for next replay
                g_outcnt = 0;
                g_sync = 0;
            }
        }
    }
}

// ---------------------------------------------------------------- launch
extern "C" void kernel_launch(void* const* d_in, const int* in_sizes, int n_in,
                              void* d_out, int out_size) {
    const float* zi = (const float*)d_in[0];
    const float* zj = (const float*)d_in[1];
    float* out = (float*)d_out;

    static int smem_set = 0;
    if (!smem_set) {
        cudaFuncSetAttribute(simlse_tc, cudaFuncAttributeMaxDynamicSharedMemorySize,
                             SMEM_REQ);
        smem_set = 1;
    }

    simlse_tc<<<dim3(64, 2), NTHR, SMEM_REQ>>>(zi, zj, out);
}

// round 17
// speedup vs baseline: 1.0461x; 1.0461x over previous
#include <cuda_runtime.h>
#include <cuda_fp16.h>
#include <cstdint>

// NT-Xent loss. fp16 inputs (A pre-scaled by log2(e)/T), tcgen05 SS MMA
// (fp32 D), N=256 super-tiles, single wave (grid 64x2). R15 loop order
// (B-copy issued in epilogue shadow) + R11 LDTM issue (both halves queued
// back-to-back, one wait). Fused pos capture + finalize.

#define NTOT 8192
#define HALF_N 4096
#define DDIM 128
#define SCALE_EX2 20.6099291555566218f   // log2(e)/0.07
#define LN2F 0.6931471805599453f
#define NSUP 16
#define NTHR 512

#if defined(__CUDA_ARCH__) && (defined(__CUDA_ARCH_FEAT_SM103_ALL) || defined(__CUDA_ARCH_SPECIFIC__))
#define HAS_TCGEN05 1
#else
#define HAS_TCGEN05 0
#endif

__device__ __half g_ZA[NTOT * DDIM];   // unit rows * SCALE_EX2 (A operand)
__device__ __half g_ZB[NTOT * DDIM];   // unit rows (B operand)
__device__ float g_rowsum[NTOT];
__device__ float g_posv[NTOT];
__device__ float g_accum;
__device__ int   g_outcnt;
__device__ int   g_blkdone[64];

// ---------------------------------------------------------------- common utils
__device__ __forceinline__ float fexp2(float x) {
    float y;
    asm("ex2.approx.f32 %0, %1;" : "=f"(y) : "f"(x));
    return y;
}
__device__ __forceinline__ void cp_async16(uint32_t dst, const void* src) {
    asm volatile("cp.async.cg.shared.global [%0], [%1], 16;"
                 :: "r"(dst), "l"(src) : "memory");
}
__device__ __forceinline__ void cp_commit() {
    asm volatile("cp.async.commit_group;" ::: "memory");
}
template <int N>
__device__ __forceinline__ void cp_wait() {
    asm volatile("cp.async.wait_group %0;" :: "n"(N) : "memory");
}

// ---------------------------------------------------------------- kernel 1
__global__ __launch_bounds__(256) void norm_kernel(const float* __restrict__ zi,
                                                   const float* __restrict__ zj) {
    int warpId = threadIdx.x >> 5;
    int lane = threadIdx.x & 31;
    int row = blockIdx.x * 8 + warpId;
    const float* src = (row < HALF_N) ? (zi + (size_t)row * DDIM)
                                      : (zj + (size_t)(row - HALF_N) * DDIM);
    float4 v = ((const float4*)src)[lane];
    float ss = v.x * v.x + v.y * v.y + v.z * v.z + v.w * v.w;
#pragma unroll
    for (int off = 16; off > 0; off >>= 1)
        ss += __shfl_xor_sync(0xffffffffu, ss, off);
    float s = rsqrtf(fmaxf(ss, 1e-24f));
    float sA = s * SCALE_EX2;
    __half2* dstB = (__half2*)(g_ZB + (size_t)row * DDIM);
    dstB[lane * 2 + 0] = __floats2half2_rn(v.x * s, v.y * s);
    dstB[lane * 2 + 1] = __floats2half2_rn(v.z * s, v.w * s);
    __half2* dstA = (__half2*)(g_ZA + (size_t)row * DDIM);
    dstA[lane * 2 + 0] = __floats2half2_rn(v.x * sA, v.y * sA);
    dstA[lane * 2 + 1] = __floats2half2_rn(v.z * sA, v.w * sA);
    if (lane == 0) g_rowsum[row] = 0.0f;
    if (blockIdx.x == 0) {
        if (threadIdx.x < 64) g_blkdone[threadIdx.x] = 0;
        if (threadIdx.x == 64) { g_accum = 0.0f; g_outcnt = 0; }
    }
}

// ---------------------------------------------------------------- kernel 2
#define SM_A    0
#define SM_B0   32768
#define SM_B1   98304
#define SM_CTRL 163840
#define SMEM_REQ (163904 + 1024)

#if HAS_TCGEN05
// ---------------- tcgen05 helpers (sm_103a pass only) ----------------
__device__ __forceinline__ uint32_t elect_one() {
    uint32_t p;
    asm volatile("{\n\t.reg .pred p;\n\telect.sync _|p, 0xFFFFFFFF;\n\t"
                 "selp.b32 %0, 1, 0, p;\n\t}" : "=r"(p));
    return p;
}
__device__ __forceinline__ void mbar_init(uint32_t a, uint32_t cnt) {
    asm volatile("mbarrier.init.shared.b64 [%0], %1;" :: "r"(a), "r"(cnt) : "memory");
}
__device__ __forceinline__ void mbar_inval(uint32_t a) {
    asm volatile("mbarrier.inval.shared.b64 [%0];" :: "r"(a) : "memory");
}
__device__ __forceinline__ void mbar_wait(uint32_t a, uint32_t phase) {
    asm volatile(
        "{\n\t.reg .pred P;\n\t"
        "W%=:\n\t"
        "mbarrier.try_wait.parity.acquire.cta.shared::cta.b64 P, [%0], %1, 0x989680;\n\t"
        "@P bra D%=;\n\t"
        "bra W%=;\n\t"
        "D%=:\n\t}"
        :: "r"(a), "r"(phase) : "memory");
}
__device__ __forceinline__ void tc_alloc(uint32_t smem_res, uint32_t ncols) {
    asm volatile("tcgen05.alloc.cta_group::1.sync.aligned.shared::cta.b32 [%0], %1;"
                 :: "r"(smem_res), "r"(ncols) : "memory");
}
__device__ __forceinline__ void tc_dealloc(uint32_t tmem, uint32_t ncols) {
    asm volatile("tcgen05.dealloc.cta_group::1.sync.aligned.b32 %0, %1;"
                 :: "r"(tmem), "r"(ncols));
}
__device__ __forceinline__ void tc_commit(uint32_t mbar) {
    asm volatile("tcgen05.commit.cta_group::1.mbarrier::arrive::one.shared::cluster.b64 [%0];"
                 :: "r"(mbar) : "memory");
}
__device__ __forceinline__ void tc_fence_before() {
    asm volatile("tcgen05.fence::before_thread_sync;" ::: "memory");
}
__device__ __forceinline__ void tc_fence_after() {
    asm volatile("tcgen05.fence::after_thread_sync;" ::: "memory");
}
__device__ __forceinline__ void tc_wait_ld() {
    asm volatile("tcgen05.wait::ld.sync.aligned;" ::: "memory");
}
__device__ __forceinline__ void fence_proxy_async_cta() {
    asm volatile("fence.proxy.async.shared::cta;" ::: "memory");
}
__device__ __forceinline__ void tc_mma_f16_ss(uint32_t d, uint64_t ad, uint64_t bd,
                                              uint32_t idesc, uint32_t en) {
    asm volatile(
        "{\n\t.reg .pred p;\n\tsetp.ne.u32 p, %4, 0;\n\t"
        "tcgen05.mma.cta_group::1.kind::f16 [%0], %1, %2, %3, {%5, %5, %5, %5}, p;\n\t}"
        :: "r"(d), "l"(ad), "l"(bd), "r"(idesc), "r"(en), "r"(0u) : "memory");
}
__device__ __forceinline__ void tc_ld_x32(uint32_t* r, uint32_t a) {
    asm volatile(
        "tcgen05.ld.sync.aligned.32x32b.x32.b32 "
        "{%0,%1,%2,%3,%4,%5,%6,%7,%8,%9,%10,%11,%12,%13,%14,%15,"
        "%16,%17,%18,%19,%20,%21,%22,%23,%24,%25,%26,%27,%28,%29,%30,%31}, [%32];"
        : "=r"(r[0]), "=r"(r[1]), "=r"(r[2]), "=r"(r[3]), "=r"(r[4]), "=r"(r[5]),
          "=r"(r[6]), "=r"(r[7]), "=r"(r[8]), "=r"(r[9]), "=r"(r[10]), "=r"(r[11]),
          "=r"(r[12]), "=r"(r[13]), "=r"(r[14]), "=r"(r[15]), "=r"(r[16]), "=r"(r[17]),
          "=r"(r[18]), "=r"(r[19]), "=r"(r[20]), "=r"(r[21]), "=r"(r[22]), "=r"(r[23]),
          "=r"(r[24]), "=r"(r[25]), "=r"(r[26]), "=r"(r[27]), "=r"(r[28]), "=r"(r[29]),
          "=r"(r[30]), "=r"(r[31])
        : "r"(a));
}
// SMEM desc: SW128, version 1 (Blackwell), SBO=64, LBO=1 (K-major)
static __device__ __forceinline__ uint64_t mk_desc(uint32_t addr) {
    return (2ull << 61) | (1ull << 46) | (64ull << 32) | (1ull << 16) |
           ((uint64_t)(addr >> 4) & 0x3FFF);
}
// idesc: dtype F32 (bit4), atype/btype F16(=0), N=256, M=128
#define IDESC ((1u << 4) | (32u << 17) | (8u << 24))

// A tile: 128 rows, atom-col stride 16KB (from g_ZA, pre-scaled)
__device__ __forceinline__ void copy_tileA(uint32_t sm_dst, int gRow0, int tid) {
    const char* gbase = (const char*)g_ZA + (size_t)gRow0 * DDIM * 2;
#pragma unroll
    for (int i = 0; i < 2048 / NTHR; i++) {
        int idx = i * NTHR + tid;
        int r = idx >> 4, c = idx & 15;
        uint32_t off = (uint32_t)(r * 128 + (c & 7) * 16);
        uint32_t dst = sm_dst + (uint32_t)((c >> 3) * 16384) +
                       (off ^ ((off >> 3) & 0x70));
        cp_async16(dst, gbase + r * 256 + c * 16);
    }
}
// B super-tile: 256 rows, atom-col stride 32KB (from g_ZB, unit)
__device__ __forceinline__ void copy_tileB(uint32_t sm_dst, int gRow0, int tid) {
    const char* gbase = (const char*)g_ZB + (size_t)gRow0 * DDIM * 2;
#pragma unroll
    for (int i = 0; i < 4096 / NTHR; i++) {
        int idx = i * NTHR + tid;
        int r = idx >> 4, c = idx & 15;
        uint32_t off = (uint32_t)(r * 128 + (c & 7) * 16);
        uint32_t dst = sm_dst + (uint32_t)((c >> 3) * 32768) +
                       (off ^ ((off >> 3) & 0x70));
        cp_async16(dst, gbase + r * 256 + c * 16);
    }
}

// FAST: 32 PRE-SCALED fp32 logits -> sum of exp2 (no FMUL, no compares).
__device__ __forceinline__ float expfast32(const uint32_t* r) {
    __half2 s0 = __float2half2_rn(0.0f), s1 = s0;
#pragma unroll
    for (int w = 0; w < 32; w += 4) {
        uint32_t p0, p1, e0, e1;
        asm("cvt.rn.f16x2.f32 %0, %1, %2;" : "=r"(p0)
            : "f"(__uint_as_float(r[w + 1])), "f"(__uint_as_float(r[w])));
        asm("cvt.rn.f16x2.f32 %0, %1, %2;" : "=r"(p1)
            : "f"(__uint_as_float(r[w + 3])), "f"(__uint_as_float(r[w + 2])));
        asm("ex2.approx.f16x2 %0, %1;" : "=r"(e0) : "r"(p0));
        asm("ex2.approx.f16x2 %0, %1;" : "=r"(e1) : "r"(p1));
        s0 = __hadd2(s0, *(__half2*)&e0);
        s1 = __hadd2(s1, *(__half2*)&e1);
    }
    float2 f = __half22float2(__hadd2(s0, s1));
    return f.x + f.y;
}

// SLOW (diag/pos tiles): pos capture (scaled) + positional diag mask.
__device__ __forceinline__ float expslow32(const uint32_t* r, int pm, int dm,
                                           float* posDot) {
    __half2 s0 = __float2half2_rn(0.0f), s1 = s0;
#pragma unroll
    for (int w = 0; w < 32; w += 2) {
        float v0 = __uint_as_float(r[w]);
        float v1 = __uint_as_float(r[w + 1]);
        if (w == pm)     *posDot = v0;
        if (w + 1 == pm) *posDot = v1;
        float x0 = (w == dm)     ? -1e4f : v0;
        float x1 = (w + 1 == dm) ? -1e4f : v1;
        uint32_t p, e;
        asm("cvt.rn.f16x2.f32 %0, %1, %2;" : "=r"(p) : "f"(x1), "f"(x0));
        asm("ex2.approx.f16x2 %0, %1;" : "=r"(e) : "r"(p));
        if (w & 2) s1 = __hadd2(s1, *(__half2*)&e);
        else       s0 = __hadd2(s0, *(__half2*)&e);
    }
    float2 f = __half22float2(__hadd2(s0, s1));
    return f.x + f.y;
}
#endif  // HAS_TCGEN05

#if !HAS_TCGEN05
#define PAD 136
__device__ __forceinline__ void ldmatrix_x4(uint32_t* r, const void* p) {
    uint32_t sa = (uint32_t)__cvta_generic_to_shared(p);
    asm volatile("ldmatrix.sync.aligned.m8n8.x4.shared.b16 {%0,%1,%2,%3}, [%4];"
                 : "=r"(r[0]), "=r"(r[1]), "=r"(r[2]), "=r"(r[3]) : "r"(sa));
}
__device__ __forceinline__ void mma16816(float* d, const uint32_t* a,
                                          uint32_t b0, uint32_t b1) {
    asm volatile(
        "mma.sync.aligned.m16n8k16.row.col.f32.f16.f16.f32 "
        "{%0,%1,%2,%3}, {%4,%5,%6,%7}, {%8,%9}, {%0,%1,%2,%3};"
        : "+f"(d[0]), "+f"(d[1]), "+f"(d[2]), "+f"(d[3])
        : "r"(a[0]), "r"(a[1]), "r"(a[2]), "r"(a[3]), "r"(b0), "r"(b1));
}
#endif

__global__ void __launch_bounds__(NTHR, 1) simlse_tc(float* __restrict__ out) {
    extern __shared__ char dsm[];
    int tid = threadIdx.x;
    int lane = tid & 31;
    int wid = tid >> 5;
    int rowBase = blockIdx.x * 128;

#if HAS_TCGEN05
    // ===== tcgen05 body: R15 loop order + both LDTM halves queued at once ====
    uint32_t raw = (uint32_t)__cvta_generic_to_shared(dsm);
    uint32_t base = (raw + 1023u) & ~1023u;
    int sup0 = blockIdx.y * NSUP;

    if (wid == 0) tc_alloc(base + SM_CTRL, 512);
    if (tid == 0) { mbar_init(base + SM_CTRL + 8, 1); mbar_init(base + SM_CTRL + 16, 1); }
    __syncthreads();
    uint32_t tmem;
    asm volatile("ld.shared.b32 %0, [%1];" : "=r"(tmem) : "r"(base + SM_CTRL));

    copy_tileA(base + SM_A, rowBase, tid);
    copy_tileB(base + SM_B0, sup0 * 256, tid);
    cp_commit();

    uint64_t descA = mk_desc(base + SM_A);
    const uint32_t kOffA[8] = {0, 2, 4, 6, 1024, 1026, 1028, 1030};
    const uint32_t kOffB[8] = {0, 2, 4, 6, 2048, 2050, 2052, 2054};

    uint32_t phase0 = 0, phase1 = 0;
    float rowAcc = 0.0f, posDot = 0.0f;
    bool havePos = false;
    int myRow = rowBase + (wid & 3) * 32 + lane;
    int partner = myRow ^ 4096;
    int partnerBase = rowBase ^ 4096;
    uint32_t tsub = ((uint32_t)(wid & 3)) << 21;
    uint32_t wordOff = (uint32_t)((wid >> 2) * 64);
    int colOff = (wid >> 2) * 64;

    for (int t = 0; t < NSUP; t++) {
        int buf = t & 1;
        // (1) B[t] resident block-wide (copy issued a full epilogue ago)
        cp_wait<0>();
        fence_proxy_async_cta();
        __syncthreads();
        // (2) issue MMA(t) into D[buf] (epilogue(t-2) done before this sync)
        if (wid == 0 && elect_one()) {
            uint64_t descB = mk_desc(base + (buf ? SM_B1 : SM_B0));
            uint32_t dAddr = tmem + buf * 256;
#pragma unroll
            for (int ks = 0; ks < 8; ks++)
                tc_mma_f16_ss(dAddr, descA + kOffA[ks], descB + kOffB[ks], IDESC, ks > 0);
            tc_commit(base + SM_CTRL + 8 + 8 * buf);
        }
        // (3) epilogue(t-1): wait MMA(t-1), queue BOTH LDTM halves, issue
        //     B[t+1] copy (old buffer freed by MMA(t-1) done), consume.
        if (t > 0) {
            int pb = (t - 1) & 1;
            mbar_wait(base + SM_CTRL + 8 + 8 * pb, pb ? phase1 : phase0);
            if (pb) phase1 ^= 1; else phase0 ^= 1;
            tc_fence_after();
            uint32_t dPrev = tmem + (uint32_t)pb * 256 + tsub + wordOff;
            uint32_t r0[32], r1[32];
            tc_ld_x32(r0, dPrev);
            tc_ld_x32(r1, dPrev + 32);
            if (t < NSUP - 1) {
                copy_tileB(base + (((t + 1) & 1) ? SM_B1 : SM_B0),
                           (sup0 + t + 1) * 256, tid);
                cp_commit();
            }
            int colBase = (sup0 + t - 1) * 256;
            bool special = ((unsigned)(rowBase - colBase) < 256u) ||
                           ((unsigned)(partnerBase - colBase) < 256u);
            int gc0 = colBase + colOff;
            int pm = partner - gc0;
            int dm = ((unsigned)(rowBase - colBase) < 256u) ? (myRow - gc0) : -100;
            tc_wait_ld();   // both halves ready
            if (special) {
                rowAcc += expslow32(r0, pm, dm, &posDot);
                rowAcc += expslow32(r1, pm - 32, dm - 32, &posDot);
                if ((unsigned)pm < 64u) havePos = true;
            } else {
                rowAcc += expfast32(r0);
                rowAcc += expfast32(r1);
            }
            tc_fence_before();
        } else {
            // t == 0: issue copy B[1] (buffer 1 untouched, no wait needed)
            copy_tileB(base + SM_B1, (sup0 + 1) * 256, tid);
            cp_commit();
        }
    }
    // final epilogue (t = NSUP-1)
    {
        int pt = NSUP - 1;
        int pb = pt & 1;
        mbar_wait(base + SM_CTRL + 8 + 8 * pb, pb ? phase1 : phase0);
        tc_fence_after();
        int colBase = (sup0 + pt) * 256;
        uint32_t dPrev = tmem + (uint32_t)pb * 256 + tsub + wordOff;
        bool special = ((unsigned)(rowBase - colBase) < 256u) ||
                       ((unsigned)(partnerBase - colBase) < 256u);
        int gc0 = colBase + colOff;
        int pm = partner - gc0;
        int dm = ((unsigned)(rowBase - colBase) < 256u) ? (myRow - gc0) : -100;
        uint32_t r0[32], r1[32];
        tc_ld_x32(r0, dPrev);
        tc_ld_x32(r1, dPrev + 32);
        tc_wait_ld();
        if (special) {
            rowAcc += expslow32(r0, pm, dm, &posDot);
            rowAcc += expslow32(r1, pm - 32, dm - 32, &posDot);
            if ((unsigned)pm < 64u) havePos = true;
        } else {
            rowAcc += expfast32(r0);
            rowAcc += expfast32(r1);
        }
        tc_fence_before();
    }

    atomicAdd(&g_rowsum[myRow], rowAcc);
    if (havePos) g_posv[myRow] = posDot;

    __syncthreads();
    if (tid == 0) { mbar_inval(base + SM_CTRL + 8); mbar_inval(base + SM_CTRL + 16); }
    __syncthreads();
    if (wid == 0) tc_dealloc(tmem, 512);

#else
    // ================= mma.sync fallback body (warps 8-15 mostly idle) =======
#define NCOLT_FB 32
    __half* sT = (__half*)dsm;
    int warpM = wid & 3;
    int warpN = wid >> 2;
    int mBase = warpM * 32;
    int nBase = warpN * 64;

    for (int idx = tid; idx < 2048; idx += NTHR) {
        int r = idx >> 4, c = idx & 15;
        *(int4*)(&sT[r * PAD + c * 8]) =
            ((const int4*)(g_ZB + (size_t)rowBase * DDIM))[r * 16 + c];
    }
    __syncthreads();

    uint32_t aF[8][2][4];
    if (wid < 8) {
#pragma unroll
        for (int ks = 0; ks < 8; ks++)
#pragma unroll
            for (int am = 0; am < 2; am++) {
                const __half* p =
                    &sT[(mBase + am * 16 + (lane & 15)) * PAD + ks * 16 + (lane >> 4) * 8];
                ldmatrix_x4(aF[ks][am], p);
            }
    }
    __syncthreads();

    float rowAcc[2][2] = {{0.f, 0.f}, {0.f, 0.f}};

    for (int ct = 0; ct < NCOLT_FB; ct++) {
        int colBase = blockIdx.y * (NCOLT_FB * 128) + ct * 128;
        for (int idx = tid; idx < 2048; idx += NTHR) {
            int r = idx >> 4, c = idx & 15;
            *(int4*)(&sT[r * PAD + c * 8]) =
                ((const int4*)(g_ZB + (size_t)colBase * DDIM))[r * 16 + c];
        }
        __syncthreads();

        if (wid < 8) {
            float acc[2][8][4];
#pragma unroll
            for (int am = 0; am < 2; am++)
#pragma unroll
                for (int an = 0; an < 8; an++)
#pragma unroll
                    for (int v = 0; v < 4; v++) acc[am][an][v] = 0.0f;

#pragma unroll
            for (int ks = 0; ks < 8; ks++) {
                uint32_t bF[4][4];
#pragma unroll
                for (int bn = 0; bn < 4; bn++) {
                    const __half* p =
                        &sT[(nBase + bn * 16 + (lane & 15)) * PAD + ks * 16 + (lane >> 4) * 8];
                    ldmatrix_x4(bF[bn], p);
                }
#pragma unroll
                for (int am = 0; am < 2; am++)
#pragma unroll
                    for (int an = 0; an < 8; an++) {
                        uint32_t b0 = bF[an >> 1][(an & 1)];
                        uint32_t b1 = bF[an >> 1][2 + (an & 1)];
                        mma16816(acc[am][an], aF[ks][am], b0, b1);
                    }
            }

            bool diag = (rowBase == colBase);
#pragma unroll
            for (int am = 0; am < 2; am++)
#pragma unroll
                for (int an = 0; an < 8; an++)
#pragma unroll
                    for (int v = 0; v < 4; v++) {
                        float a = acc[am][an][v];
                        int rl = mBase + am * 16 + (lane >> 2) + ((v >> 1) << 3);
                        int cl = nBase + an * 8 + ((lane & 3) << 1) + (v & 1);
                        int grow = rowBase + rl;
                        int gcol = colBase + cl;
                        if (gcol == (grow ^ 4096)) g_posv[grow] = a * SCALE_EX2;
                        float e = fexp2(a * SCALE_EX2);
                        if (diag && rl == cl) e = 0.0f;
                        rowAcc[am][v >> 1] += e;
                    }
        }
        __syncthreads();
    }

    if (wid < 8) {
#pragma unroll
        for (int am = 0; am < 2; am++)
#pragma unroll
            for (int h = 0; h < 2; h++) {
                float r = rowAcc[am][h];
                r += __shfl_xor_sync(0xffffffffu, r, 1);
                r += __shfl_xor_sync(0xffffffffu, r, 2);
                if ((lane & 3) == 0) {
                    int gr = rowBase + mBase + am * 16 + (lane >> 2) + h * 8;
                    atomicAdd(&g_rowsum[gr], r);
                }
            }
    }
#endif

    // ============== shared tail: last CTA of row-block reduces ==============
    __shared__ int lastFlag;
    __shared__ float red[16];
    __threadfence();
    __syncthreads();
    if (tid == 0) {
        int old = atomicAdd(&g_blkdone[blockIdx.x], 1);
        lastFlag = (old == (int)gridDim.y - 1) ? 1 : 0;
    }
    __syncthreads();
    if (lastFlag) {
        __threadfence();
        float v = 0.0f;
        if (tid < 128) {
            int row = rowBase + tid;
            float rs = *(volatile float*)&g_rowsum[row];
            float pd = *(volatile float*)&g_posv[row];   // pre-scaled by SCALE_EX2
            v = __logf(rs) - pd * LN2F;
        }
#pragma unroll
        for (int off = 16; off > 0; off >>= 1)
            v += __shfl_xor_sync(0xffffffffu, v, off);
        if (lane == 0 && wid < 16) red[wid] = v;
        __syncthreads();
        if (tid == 0) {
            float b = 0.0f;
#pragma unroll
            for (int w = 0; w < NTHR / 32; w++) b += red[w];
            atomicAdd(&g_accum, b);
            __threadfence();
            int old2 = atomicAdd(&g_outcnt, 1);
            if (old2 == 63)
                out[0] = atomicAdd(&g_accum, 0.0f) * (1.0f / (float)NTOT);
        }
    }
}

// ---------------------------------------------------------------- launch
extern "C" void kernel_launch(void* const* d_in, const int* in_sizes, int n_in,
                              void* d_out, int out_size) {
    const float* zi = (const float*)d_in[0];
    const float* zj = (const float*)d_in[1];
    float* out = (float*)d_out;

    static int smem_set = 0;
    if (!smem_set) {
        cudaFuncSetAttribute(simlse_tc, cudaFuncAttributeMaxDynamicSharedMemorySize,
                             SMEM_REQ);
        smem_set = 1;
    }

    norm_kernel<<<NTOT / 8, 256>>>(zi, zj);
    simlse_tc<<<dim3(64, 2), NTHR, SMEM_REQ>>>(out);
}